// round 1
// baseline (speedup 1.0000x reference)
#include <cuda_runtime.h>
#include <cuda_fp16.h>
#include <mma.h>

using namespace nvcuda;

#define B_   32
#define S_   4096
#define D_   1024
#define H_   512
#define BM   64
#define BK   32
#define BPAD 528
#define NSPLIT 16

__device__ __align__(16) __half g_W1h[D_ * H_];
__device__ float  g_scores[B_ * S_];
__device__ float  g_weights[B_ * S_];
__device__ float  g_partials[NSPLIT * B_ * D_];

// ---------------- K0: W1 fp32 -> fp16 ----------------
__global__ void convert_w1_kernel(const float* __restrict__ W1) {
    int i = blockIdx.x * blockDim.x + threadIdx.x;
    if (i < D_ * H_) g_W1h[i] = __float2half(W1[i]);
}

// ---------------- K1: fused scores ----------------
// scores[b,s] = w2 . ReLU( (x[b,s,:]*prev[b,:]) @ W1 + b1 ) + b2
// BM=64 rows per CTA, full D staged in smem as fp16, K-chunked W1 staging,
// 16 warps: warp tile 32 rows x 64 cols of the 64x512 hidden block.
__global__ void __launch_bounds__(512, 1)
scores_kernel(const float* __restrict__ x, const float* __restrict__ prev,
              const float* __restrict__ b1, const float* __restrict__ w2,
              const float* __restrict__ b2) {
    extern __shared__ char smem_raw[];
    __half* Ah = (__half*)smem_raw;                 // BM * D_ halves (131072 B)
    __half* Bs = Ah + (size_t)BM * D_;              // BK * BPAD halves (33792 B)
    float*  ps = (float*)(Bs + (size_t)BK * BPAD);  // D_ floats (4096 B)
    float*  scoreBuf = ps + D_;                     // BM floats
    float*  stage = scoreBuf + BM;                  // 16 warps * 16*20 floats

    const int tid  = threadIdx.x;
    const int warp = tid >> 5;
    const int lane = tid & 31;
    const int b  = blockIdx.y;
    const int s0 = blockIdx.x * BM;

    for (int i = tid; i < D_; i += 512) ps[i] = prev[b * D_ + i];
    if (tid < BM) scoreBuf[tid] = 0.f;
    __syncthreads();

    // Stage x-tile * prev as fp16, fully coalesced float4 loads.
    {
        const float4* xb = (const float4*)(x + ((size_t)b * S_ + s0) * D_);
        #pragma unroll 8
        for (int it = 0; it < 32; ++it) {
            int e4  = tid + it * 512;        // 0..16383 float4 slots
            float4 v = xb[e4];
            int col = (e4 & 255) * 4;
            int row = e4 >> 8;
            v.x *= ps[col + 0]; v.y *= ps[col + 1];
            v.z *= ps[col + 2]; v.w *= ps[col + 3];
            __half2* dst = (__half2*)(Ah + (size_t)row * D_ + col);
            dst[0] = __floats2half2_rn(v.x, v.y);
            dst[1] = __floats2half2_rn(v.z, v.w);
        }
    }

    wmma::fragment<wmma::matrix_a, 16, 16, 16, __half, wmma::row_major> af[2];
    wmma::fragment<wmma::matrix_b, 16, 16, 16, __half, wmma::row_major> bf;
    wmma::fragment<wmma::accumulator, 16, 16, 16, float> acc[2][4];
    #pragma unroll
    for (int mi = 0; mi < 2; ++mi)
        #pragma unroll
        for (int ni = 0; ni < 4; ++ni)
            wmma::fill_fragment(acc[mi][ni], 0.f);

    const int wm = warp >> 3;   // 0..1
    const int wn = warp & 7;    // 0..7

    for (int kc = 0; kc < D_; kc += BK) {
        __syncthreads();
        // Stage W1 k-chunk (fp16), coalesced 16B loads.
        {
            const uint4* src = (const uint4*)(g_W1h + (size_t)kc * H_);
            #pragma unroll
            for (int j = 0; j < 4; ++j) {
                int u   = tid + j * 512;   // 0..2047 uint4 slots (32 rows * 64)
                int row = u >> 6;
                int c8  = u & 63;
                uint4 v = src[u];
                *(uint4*)(Bs + (size_t)row * BPAD + c8 * 8) = v;
            }
        }
        __syncthreads();
        #pragma unroll
        for (int kt = 0; kt < BK; kt += 16) {
            wmma::load_matrix_sync(af[0], Ah + (size_t)(wm * 32 +  0) * D_ + kc + kt, D_);
            wmma::load_matrix_sync(af[1], Ah + (size_t)(wm * 32 + 16) * D_ + kc + kt, D_);
            #pragma unroll
            for (int ni = 0; ni < 4; ++ni) {
                wmma::load_matrix_sync(bf, Bs + (size_t)kt * BPAD + wn * 64 + ni * 16, BPAD);
                wmma::mma_sync(acc[0][ni], af[0], bf, acc[0][ni]);
                wmma::mma_sync(acc[1][ni], af[1], bf, acc[1][ni]);
            }
        }
    }
    __syncthreads();

    // Epilogue: ReLU(hidden + b1) . w2, reduced into per-row score buffer.
    float* st = stage + warp * (16 * 20);
    #pragma unroll
    for (int mi = 0; mi < 2; ++mi) {
        #pragma unroll
        for (int ni = 0; ni < 4; ++ni) {
            wmma::store_matrix_sync(st, acc[mi][ni], 20, wmma::mem_row_major);
            __syncwarp();
            int rr = lane >> 1;
            int c0 = (lane & 1) * 8;
            int hb = wn * 64 + ni * 16;
            float sum = 0.f;
            #pragma unroll
            for (int j = 0; j < 8; ++j) {
                int c = c0 + j;
                float v = st[rr * 20 + c] + __ldg(&b1[hb + c]);
                v = fmaxf(v, 0.f);
                sum += v * __ldg(&w2[hb + c]);
            }
            atomicAdd(&scoreBuf[wm * 32 + mi * 16 + rr], sum);
            __syncwarp();
        }
    }
    __syncthreads();
    if (tid < BM) g_scores[b * S_ + s0 + tid] = scoreBuf[tid] + b2[0];
}

// ---------------- K2: softmax over S ----------------
__global__ void __launch_bounds__(256)
softmax_kernel() {
    __shared__ float red[256];
    const int b = blockIdx.x, tid = threadIdx.x;
    float loc[16];
    float m = -1e30f;
    #pragma unroll
    for (int i = 0; i < 16; ++i) {
        loc[i] = g_scores[b * S_ + tid + i * 256];
        m = fmaxf(m, loc[i]);
    }
    red[tid] = m; __syncthreads();
    for (int stp = 128; stp > 0; stp >>= 1) {
        if (tid < stp) red[tid] = fmaxf(red[tid], red[tid + stp]);
        __syncthreads();
    }
    m = red[0]; __syncthreads();
    float sum = 0.f;
    #pragma unroll
    for (int i = 0; i < 16; ++i) { loc[i] = expf(loc[i] - m); sum += loc[i]; }
    red[tid] = sum; __syncthreads();
    for (int stp = 128; stp > 0; stp >>= 1) {
        if (tid < stp) red[tid] += red[tid + stp];
        __syncthreads();
    }
    float inv = 1.f / red[0];
    #pragma unroll
    for (int i = 0; i < 16; ++i)
        g_weights[b * S_ + tid + i * 256] = loc[i] * inv;
}

// ---------------- K3: split-S weighted reduction (deterministic) ----------------
__global__ void __launch_bounds__(256)
wsum_kernel(const float* __restrict__ x) {
    __shared__ float wsm[256];
    const int b = blockIdx.y, sp = blockIdx.x;
    const int tid = threadIdx.x;
    const int s0 = sp * 256;
    wsm[tid] = g_weights[b * S_ + s0 + tid];
    __syncthreads();
    const float4* base = (const float4*)(x + ((size_t)b * S_ + s0) * D_) + tid;
    float4 acc = make_float4(0.f, 0.f, 0.f, 0.f);
    #pragma unroll 8
    for (int i = 0; i < 256; ++i) {
        float w  = wsm[i];
        float4 v = base[(size_t)i * (D_ / 4)];
        acc.x += w * v.x; acc.y += w * v.y;
        acc.z += w * v.z; acc.w += w * v.w;
    }
    ((float4*)(g_partials + ((size_t)sp * B_ + b) * D_))[tid] = acc;
}

// ---------------- K4: final reduce over splits ----------------
__global__ void reduce_kernel(float* __restrict__ out) {
    const int b = blockIdx.x, d = threadIdx.x;
    float s = 0.f;
    #pragma unroll
    for (int sp = 0; sp < NSPLIT; ++sp)
        s += g_partials[((size_t)sp * B_ + b) * D_ + d];
    out[b * D_ + d] = s;
}

extern "C" void kernel_launch(void* const* d_in, const int* in_sizes, int n_in,
                              void* d_out, int out_size) {
    const float* x    = (const float*)d_in[0];
    const float* prev = (const float*)d_in[1];
    const float* W1   = (const float*)d_in[2];
    const float* b1   = (const float*)d_in[3];
    const float* w2   = (const float*)d_in[4];
    const float* b2   = (const float*)d_in[5];
    float* out = (float*)d_out;

    const size_t smem = (size_t)BM * D_ * 2      // Ah
                      + (size_t)BK * BPAD * 2    // Bs
                      + (size_t)D_ * 4           // ps
                      + (size_t)BM * 4           // scoreBuf
                      + (size_t)16 * 16 * 20 * 4; // stage
    cudaFuncSetAttribute(scores_kernel, cudaFuncAttributeMaxDynamicSharedMemorySize, (int)smem);

    convert_w1_kernel<<<(D_ * H_ + 255) / 256, 256>>>(W1);
    scores_kernel<<<dim3(S_ / BM, B_), 512, smem>>>(x, prev, b1, w2, b2);
    softmax_kernel<<<B_, 256>>>();
    wsum_kernel<<<dim3(NSPLIT, B_), 256>>>(x);
    reduce_kernel<<<B_, 1024>>>(out);
}

// round 2
// speedup vs baseline: 2.2712x; 2.2712x over previous
#include <cuda_runtime.h>
#include <cuda_fp16.h>
#include <mma.h>

using namespace nvcuda;

#define B_   32
#define S_   4096
#define D_   1024
#define H_   512
#define BM   64
#define BKC  64           // K-chunk
#define NCH  (D_ / BKC)   // 16 chunks
#define APAD 72           // Ah row stride (halves): 144B -> 4-bank shift/row
#define BPADB 520         // Bs row stride (halves): 1040B -> 4-bank shift/row
#define NSPLIT 16

__device__ __align__(16) __half g_W1h[D_ * H_];
__device__ float  g_scores[B_ * S_];
__device__ float  g_weights[B_ * S_];
__device__ float  g_partials[NSPLIT * B_ * D_];

__device__ __forceinline__ void cp_async16(void* smem, const void* gmem) {
    unsigned s = (unsigned)__cvta_generic_to_shared(smem);
    asm volatile("cp.async.cg.shared.global [%0], [%1], 16;\n" :: "r"(s), "l"(gmem));
}
__device__ __forceinline__ void cp_async_commit() {
    asm volatile("cp.async.commit_group;\n");
}
__device__ __forceinline__ void cp_async_wait_all() {
    asm volatile("cp.async.wait_group 0;\n");
}

// ---------------- K0: W1 fp32 -> fp16 ----------------
__global__ void convert_w1_kernel(const float* __restrict__ W1) {
    int i = blockIdx.x * blockDim.x + threadIdx.x;
    if (i < D_ * H_) g_W1h[i] = __float2half(W1[i]);
}

// ---------------- K1: fused scores, double-buffered K-chunk pipeline ----------------
// scores[b,s] = w2 . ReLU( (x[b,s,:]*prev[b,:]) @ W1 + b1 ) + b2
__global__ void __launch_bounds__(512, 1)
scores_kernel(const float* __restrict__ x, const float* __restrict__ prev,
              const float* __restrict__ b1, const float* __restrict__ w2,
              const float* __restrict__ b2) {
    extern __shared__ char smem_raw[];
    __half* Ah = (__half*)smem_raw;                       // 2 * BM * APAD halves
    __half* Bs = Ah + 2 * BM * APAD;                      // 2 * BKC * BPADB halves
    float*  ps = (float*)(Bs + 2 * BKC * BPADB);          // D_ floats
    float*  scoreBuf = ps + D_;                           // BM floats
    float*  stage = scoreBuf + BM;                        // 16 warps * 16*20 floats

    const int tid  = threadIdx.x;
    const int warp = tid >> 5;
    const int lane = tid & 31;
    const int b  = blockIdx.y;
    const int s0 = blockIdx.x * BM;

    const float* xb = x + ((size_t)b * S_ + s0) * D_;

    for (int i = tid; i < D_; i += 512) ps[i] = prev[b * D_ + i];
    if (tid < BM) scoreBuf[tid] = 0.f;
    __syncthreads();   // ps ready (needed by A conversion below)

    // Per-thread A-chunk slots: e4 = tid + j*512, j=0..1 ; row=e4>>4, c4=e4&15
    const int arow0 = tid >> 4;          // 0..31
    const int ac4   = tid & 15;          // 0..15
    // second slot: e4 = tid+512 -> row = arow0 + 32, same c4

    // ---- prologue: stage chunk 0 into buffer 0 ----
    {
        const int kc = 0;
        #pragma unroll
        for (int j = 0; j < 2; ++j) {
            int row = arow0 + j * 32;
            float4 v = *(const float4*)(xb + (size_t)row * D_ + kc + ac4 * 4);
            int k0 = kc + ac4 * 4;
            v.x *= ps[k0 + 0]; v.y *= ps[k0 + 1];
            v.z *= ps[k0 + 2]; v.w *= ps[k0 + 3];
            __half2* dst = (__half2*)(Ah + (size_t)row * APAD + ac4 * 4);
            dst[0] = __floats2half2_rn(v.x, v.y);
            dst[1] = __floats2half2_rn(v.z, v.w);
        }
        #pragma unroll
        for (int j = 0; j < 8; ++j) {
            int u   = tid + j * 512;     // 0..4095
            int row = u >> 6;            // 0..63
            int c16 = u & 63;
            cp_async16(Bs + (size_t)row * BPADB + c16 * 8,
                       g_W1h + (size_t)(kc + row) * H_ + c16 * 8);
        }
        cp_async_commit();
    }

    wmma::fragment<wmma::matrix_a, 16, 16, 16, __half, wmma::row_major> af[2];
    wmma::fragment<wmma::matrix_b, 16, 16, 16, __half, wmma::row_major> bf;
    wmma::fragment<wmma::accumulator, 16, 16, 16, float> acc[2][4];
    #pragma unroll
    for (int mi = 0; mi < 2; ++mi)
        #pragma unroll
        for (int ni = 0; ni < 4; ++ni)
            wmma::fill_fragment(acc[mi][ni], 0.f);

    const int wm = warp >> 3;   // 0..1 (32-row halves)
    const int wn = warp & 7;    // 0..7 (64-col slices)

    float4 pref[2];

    for (int i = 0; i < NCH; ++i) {
        const int cur = i & 1;
        const int nxt = cur ^ 1;

        // Prefetch next A chunk to registers (overlaps with wait+barrier+mma)
        if (i + 1 < NCH) {
            const int kc2 = (i + 1) * BKC;
            #pragma unroll
            for (int j = 0; j < 2; ++j) {
                int row = arow0 + j * 32;
                pref[j] = *(const float4*)(xb + (size_t)row * D_ + kc2 + ac4 * 4);
            }
        }

        cp_async_wait_all();
        __syncthreads();        // buffer `cur` fully staged & visible

        // Stage next chunk into `nxt` (overlaps with mma on `cur`)
        if (i + 1 < NCH) {
            const int kc2 = (i + 1) * BKC;
            #pragma unroll
            for (int j = 0; j < 2; ++j) {
                int row = arow0 + j * 32;
                float4 v = pref[j];
                int k0 = kc2 + ac4 * 4;
                v.x *= ps[k0 + 0]; v.y *= ps[k0 + 1];
                v.z *= ps[k0 + 2]; v.w *= ps[k0 + 3];
                __half2* dst = (__half2*)(Ah + (size_t)nxt * BM * APAD
                                             + (size_t)row * APAD + ac4 * 4);
                dst[0] = __floats2half2_rn(v.x, v.y);
                dst[1] = __floats2half2_rn(v.z, v.w);
            }
            #pragma unroll
            for (int j = 0; j < 8; ++j) {
                int u   = tid + j * 512;
                int row = u >> 6;
                int c16 = u & 63;
                cp_async16(Bs + (size_t)nxt * BKC * BPADB + (size_t)row * BPADB + c16 * 8,
                           g_W1h + (size_t)(kc2 + row) * H_ + c16 * 8);
            }
            cp_async_commit();
        }

        // MMA on buffer `cur`
        const __half* Ab = Ah + (size_t)cur * BM * APAD;
        const __half* Bb = Bs + (size_t)cur * BKC * BPADB;
        #pragma unroll
        for (int kt = 0; kt < BKC; kt += 16) {
            wmma::load_matrix_sync(af[0], Ab + (size_t)(wm * 32 +  0) * APAD + kt, APAD);
            wmma::load_matrix_sync(af[1], Ab + (size_t)(wm * 32 + 16) * APAD + kt, APAD);
            #pragma unroll
            for (int ni = 0; ni < 4; ++ni) {
                wmma::load_matrix_sync(bf, Bb + (size_t)kt * BPADB + wn * 64 + ni * 16, BPADB);
                wmma::mma_sync(acc[0][ni], af[0], bf, acc[0][ni]);
                wmma::mma_sync(acc[1][ni], af[1], bf, acc[1][ni]);
            }
        }
        // No trailing barrier: iteration i+1's top barrier orders writes into `nxt`
        // (and i+2's writes into `cur`) against this iteration's reads.
    }
    __syncthreads();

    // Epilogue: ReLU(hidden + b1) . w2 -> per-row partials -> scoreBuf
    float* st = stage + warp * (16 * 20);
    #pragma unroll
    for (int mi = 0; mi < 2; ++mi) {
        float rowsum = 0.f;
        #pragma unroll
        for (int ni = 0; ni < 4; ++ni) {
            wmma::store_matrix_sync(st, acc[mi][ni], 20, wmma::mem_row_major);
            __syncwarp();
            int rr = lane >> 1;
            int c0 = (lane & 1) * 8;
            int hb = wn * 64 + ni * 16;
            float sum = 0.f;
            #pragma unroll
            for (int j = 0; j < 8; ++j) {
                int c = c0 + j;
                float v = st[rr * 20 + c] + __ldg(&b1[hb + c]);
                v = fmaxf(v, 0.f);
                sum += v * __ldg(&w2[hb + c]);
            }
            rowsum += sum;
            __syncwarp();
        }
        rowsum += __shfl_xor_sync(0xffffffffu, rowsum, 1);
        if ((lane & 1) == 0)
            atomicAdd(&scoreBuf[wm * 32 + mi * 16 + (lane >> 1)], rowsum);
    }
    __syncthreads();
    if (tid < BM) g_scores[b * S_ + s0 + tid] = scoreBuf[tid] + b2[0];
}

// ---------------- K2: softmax over S ----------------
__global__ void __launch_bounds__(256)
softmax_kernel() {
    __shared__ float red[256];
    const int b = blockIdx.x, tid = threadIdx.x;
    float loc[16];
    float m = -1e30f;
    #pragma unroll
    for (int i = 0; i < 16; ++i) {
        loc[i] = g_scores[b * S_ + tid + i * 256];
        m = fmaxf(m, loc[i]);
    }
    red[tid] = m; __syncthreads();
    for (int stp = 128; stp > 0; stp >>= 1) {
        if (tid < stp) red[tid] = fmaxf(red[tid], red[tid + stp]);
        __syncthreads();
    }
    m = red[0]; __syncthreads();
    float sum = 0.f;
    #pragma unroll
    for (int i = 0; i < 16; ++i) { loc[i] = expf(loc[i] - m); sum += loc[i]; }
    red[tid] = sum; __syncthreads();
    for (int stp = 128; stp > 0; stp >>= 1) {
        if (tid < stp) red[tid] += red[tid + stp];
        __syncthreads();
    }
    float inv = 1.f / red[0];
    #pragma unroll
    for (int i = 0; i < 16; ++i)
        g_weights[b * S_ + tid + i * 256] = loc[i] * inv;
}

// ---------------- K3: split-S weighted reduction (deterministic) ----------------
__global__ void __launch_bounds__(256)
wsum_kernel(const float* __restrict__ x) {
    __shared__ float wsm[256];
    const int b = blockIdx.y, sp = blockIdx.x;
    const int tid = threadIdx.x;
    const int s0 = sp * 256;
    wsm[tid] = g_weights[b * S_ + s0 + tid];
    __syncthreads();
    const float4* base = (const float4*)(x + ((size_t)b * S_ + s0) * D_) + tid;
    float4 acc = make_float4(0.f, 0.f, 0.f, 0.f);
    #pragma unroll 8
    for (int i = 0; i < 256; ++i) {
        float w  = wsm[i];
        float4 v = base[(size_t)i * (D_ / 4)];
        acc.x += w * v.x; acc.y += w * v.y;
        acc.z += w * v.z; acc.w += w * v.w;
    }
    ((float4*)(g_partials + ((size_t)sp * B_ + b) * D_))[tid] = acc;
}

// ---------------- K4: final reduce over splits ----------------
__global__ void reduce_kernel(float* __restrict__ out) {
    const int b = blockIdx.x, d = threadIdx.x;
    float s = 0.f;
    #pragma unroll
    for (int sp = 0; sp < NSPLIT; ++sp)
        s += g_partials[((size_t)sp * B_ + b) * D_ + d];
    out[b * D_ + d] = s;
}

extern "C" void kernel_launch(void* const* d_in, const int* in_sizes, int n_in,
                              void* d_out, int out_size) {
    const float* x    = (const float*)d_in[0];
    const float* prev = (const float*)d_in[1];
    const float* W1   = (const float*)d_in[2];
    const float* b1   = (const float*)d_in[3];
    const float* w2   = (const float*)d_in[4];
    const float* b2   = (const float*)d_in[5];
    float* out = (float*)d_out;

    const size_t smem = (size_t)2 * BM * APAD * 2      // Ah double buffer
                      + (size_t)2 * BKC * BPADB * 2    // Bs double buffer
                      + (size_t)D_ * 4                 // ps
                      + (size_t)BM * 4                 // scoreBuf
                      + (size_t)16 * 16 * 20 * 4;      // stage
    cudaFuncSetAttribute(scores_kernel, cudaFuncAttributeMaxDynamicSharedMemorySize, (int)smem);

    convert_w1_kernel<<<(D_ * H_ + 255) / 256, 256>>>(W1);
    scores_kernel<<<dim3(S_ / BM, B_), 512, smem>>>(x, prev, b1, w2, b2);
    softmax_kernel<<<B_, 256>>>();
    wsum_kernel<<<dim3(NSPLIT, B_), 256>>>(x);
    reduce_kernel<<<B_, 1024>>>(out);
}